// round 1
// baseline (speedup 1.0000x reference)
#include <cuda_runtime.h>
#include <math.h>

#define N_SEQ 512
#define N_RES 384
#define C_M   256
#define C_OUT 32
#define C_Z   128
#define BC    (N_RES * C_OUT)     /* 12288  (b,c) flattened */
#define NPAIR (N_RES * N_RES)     /* 147456 (b,d) pairs     */
#define KCE   (C_OUT * C_OUT)     /* 1024   (c,e) flattened */

// ---------------- scratch (device globals; no allocation allowed) ----------
__device__ float g_L[(size_t)N_SEQ * BC];          // 25.2 MB  [a, b*32+c]
__device__ float g_R[(size_t)N_SEQ * BC];          // 25.2 MB  [a, d*32+e]
__device__ float g_inter[(size_t)BC * BC];         // 604 MB   [b*32+c, d*32+e]
__device__ float g_ninv[NPAIR];                    // 1/(eps+norm[b,d])

// ---------------- Kernel 1: LayerNorm + left/right projection + mask -------
__global__ __launch_bounds__(256) void ln_proj_kernel(
    const float* __restrict__ act, const float* __restrict__ mask,
    const float* __restrict__ ln_scale, const float* __restrict__ ln_offset,
    const float* __restrict__ left_w, const float* __restrict__ left_b,
    const float* __restrict__ right_w, const float* __restrict__ right_b)
{
    int row = blockIdx.x;              // row = a*N_RES + b
    int t = threadIdx.x;               // 0..255
    __shared__ float ys[C_M];
    __shared__ float red[16];
    __shared__ float ps[16][64];

    float x = act[(size_t)row * C_M + t];
    float s = x, s2 = x * x;
    #pragma unroll
    for (int o = 16; o > 0; o >>= 1) {
        s  += __shfl_down_sync(0xffffffffu, s, o);
        s2 += __shfl_down_sync(0xffffffffu, s2, o);
    }
    int wid = t >> 5, lane = t & 31;
    if (lane == 0) { red[wid] = s; red[wid + 8] = s2; }
    __syncthreads();
    float sum = 0.f, sumsq = 0.f;
    #pragma unroll
    for (int i = 0; i < 8; i++) { sum += red[i]; sumsq += red[i + 8]; }
    float mu  = sum * (1.0f / C_M);
    float var = sumsq * (1.0f / C_M) - mu * mu;
    float y = (x - mu) * rsqrtf(var + 1e-5f) * ln_scale[t] + ln_offset[t];
    ys[t] = y;
    __syncthreads();

    // 64 outputs (32 left + 32 right). Thread layout: og = output quad (0..15),
    // ch = k-chunk (0..15, 16 k's each). float4 weight loads, coalesced.
    int og = t & 15;
    int ch = t >> 4;
    const float* Wp = (og < 8) ? (left_w + og * 4) : (right_w + (og - 8) * 4);
    float p0 = 0.f, p1 = 0.f, p2 = 0.f, p3 = 0.f;
    #pragma unroll
    for (int i = 0; i < 16; i++) {
        int k = ch * 16 + i;
        float4 w4 = *(const float4*)(Wp + (size_t)k * C_OUT);
        float yv = ys[k];
        p0 += yv * w4.x; p1 += yv * w4.y; p2 += yv * w4.z; p3 += yv * w4.w;
    }
    ps[ch][og * 4 + 0] = p0; ps[ch][og * 4 + 1] = p1;
    ps[ch][og * 4 + 2] = p2; ps[ch][og * 4 + 3] = p3;
    __syncthreads();

    if (t < 64) {
        float v = 0.f;
        #pragma unroll
        for (int c = 0; c < 16; c++) v += ps[c][t];
        float m = mask[row];
        int a = row / N_RES, b = row % N_RES;
        size_t idx = (size_t)a * BC + (size_t)b * C_OUT;
        if (t < 32) g_L[idx + t]        = m * (v + left_b[t]);
        else        g_R[idx + (t - 32)] = m * (v + right_b[t - 32]);
    }
}

// ---------------- Kernel 2: norm = mask^T mask, stored as reciprocal -------
__global__ __launch_bounds__(256) void norm_kernel(const float* __restrict__ mask)
{
    int m = blockIdx.x * 256 + threadIdx.x;     // m = b*N_RES + d
    int b = m / N_RES, d = m % N_RES;
    float s = 0.f;
    for (int a = 0; a < N_SEQ; a++)
        s += mask[a * N_RES + b] * mask[a * N_RES + d];
    g_ninv[m] = 1.0f / (1e-3f + s);
}

// ---------------- Kernel 3: GEMM1  inter = L^T R  (12288x12288, K=512) -----
// Both operands K-major -> all global loads coalesced. 128x128x8 tile,
// 8x8 microtile with split-64 conflict-free LDS pattern.
__global__ __launch_bounds__(256) void gemm1_kernel()
{
    __shared__ float As[8][128];
    __shared__ float Bs[8][128];
    int tid = threadIdx.x;
    int tx = tid & 15, ty = tid >> 4;
    int i0 = blockIdx.y * 128, j0 = blockIdx.x * 128;
    int lk = tid >> 5, li = (tid & 31) << 2;
    const float* Ap = g_L + (size_t)lk * BC + i0 + li;
    const float* Bp = g_R + (size_t)lk * BC + j0 + li;

    float acc[8][8];
    #pragma unroll
    for (int i = 0; i < 8; i++)
        #pragma unroll
        for (int j = 0; j < 8; j++) acc[i][j] = 0.f;

    float4 av = *(const float4*)Ap;
    float4 bv = *(const float4*)Bp;
    for (int kt = 0; kt < N_SEQ; kt += 8) {
        *(float4*)&As[lk][li] = av;
        *(float4*)&Bs[lk][li] = bv;
        __syncthreads();
        if (kt + 8 < N_SEQ) {
            Ap += (size_t)8 * BC; Bp += (size_t)8 * BC;
            av = *(const float4*)Ap;
            bv = *(const float4*)Bp;
        }
        #pragma unroll
        for (int k = 0; k < 8; k++) {
            float a[8], b[8];
            *(float4*)&a[0] = *(const float4*)&As[k][ty * 4];
            *(float4*)&a[4] = *(const float4*)&As[k][ty * 4 + 64];
            *(float4*)&b[0] = *(const float4*)&Bs[k][tx * 4];
            *(float4*)&b[4] = *(const float4*)&Bs[k][tx * 4 + 64];
            #pragma unroll
            for (int i = 0; i < 8; i++)
                #pragma unroll
                for (int j = 0; j < 8; j++)
                    acc[i][j] += a[i] * b[j];
        }
        __syncthreads();
    }
    #pragma unroll
    for (int i = 0; i < 8; i++) {
        int irow = i0 + ((i & 4) ? 64 : 0) + ty * 4 + (i & 3);
        #pragma unroll
        for (int h = 0; h < 2; h++) {
            float4 v = make_float4(acc[i][h * 4 + 0], acc[i][h * 4 + 1],
                                   acc[i][h * 4 + 2], acc[i][h * 4 + 3]);
            *(float4*)&g_inter[(size_t)irow * BC + j0 + h * 64 + tx * 4] = v;
        }
    }
}

// ---------------- Kernel 4: GEMM2  out = inter_gathered @ W + b, / norm ----
// M = 147456 (b,d pairs), N = 128 (full, so inter is read exactly once),
// K = 1024 (c*32+e).  A is gathered from g_inter with an smem transpose.
__global__ __launch_bounds__(256) void gemm2_kernel(
    const float* __restrict__ W,      // output_w [1024, 128]
    const float* __restrict__ ob,     // output_b [128]
    float* __restrict__ out)
{
    __shared__ float As[8][132];      // padded; transpose-on-load
    __shared__ float Bs[8][128];
    int tid = threadIdx.x;
    int tx = tid & 15, ty = tid >> 4;
    int m0 = blockIdx.x * 128;
    int lm = tid >> 1, lkq = (tid & 1) << 2;     // each thread: 1 float4 of A
    int mrow = m0 + lm;
    int bb = mrow / N_RES, dd = mrow % N_RES;
    const float* Abase = g_inter + (size_t)bb * C_OUT * BC + (size_t)dd * C_OUT;
    int bk = tid >> 5, bf = (tid & 31) << 2;

    float acc[8][8];
    #pragma unroll
    for (int i = 0; i < 8; i++)
        #pragma unroll
        for (int j = 0; j < 8; j++) acc[i][j] = 0.f;

    for (int kt = 0; kt < KCE; kt += 8) {
        int c = kt >> 5;
        int e = (kt & 31) + lkq;
        float4 av = *(const float4*)(Abase + (size_t)c * BC + e);
        As[lkq + 0][lm] = av.x; As[lkq + 1][lm] = av.y;
        As[lkq + 2][lm] = av.z; As[lkq + 3][lm] = av.w;
        *(float4*)&Bs[bk][bf] = *(const float4*)(W + (size_t)(kt + bk) * C_Z + bf);
        __syncthreads();
        #pragma unroll
        for (int k = 0; k < 8; k++) {
            float a[8], b[8];
            *(float4*)&a[0] = *(const float4*)&As[k][ty * 4];
            *(float4*)&a[4] = *(const float4*)&As[k][ty * 4 + 64];
            *(float4*)&b[0] = *(const float4*)&Bs[k][tx * 4];
            *(float4*)&b[4] = *(const float4*)&Bs[k][tx * 4 + 64];
            #pragma unroll
            for (int i = 0; i < 8; i++)
                #pragma unroll
                for (int j = 0; j < 8; j++)
                    acc[i][j] += a[i] * b[j];
        }
        __syncthreads();
    }
    #pragma unroll
    for (int i = 0; i < 8; i++) {
        int m = m0 + ((i & 4) ? 64 : 0) + ty * 4 + (i & 3);
        float inv = g_ninv[m];
        #pragma unroll
        for (int h = 0; h < 2; h++) {
            int f = h * 64 + tx * 4;
            float4 v;
            v.x = (acc[i][h * 4 + 0] + ob[f + 0]) * inv;
            v.y = (acc[i][h * 4 + 1] + ob[f + 1]) * inv;
            v.z = (acc[i][h * 4 + 2] + ob[f + 2]) * inv;
            v.w = (acc[i][h * 4 + 3] + ob[f + 3]) * inv;
            *(float4*)&out[(size_t)m * C_Z + f] = v;
        }
    }
}

// ---------------------------------------------------------------------------
extern "C" void kernel_launch(void* const* d_in, const int* in_sizes, int n_in,
                              void* d_out, int out_size)
{
    const float* act       = (const float*)d_in[0];
    const float* mask      = (const float*)d_in[1];
    const float* ln_scale  = (const float*)d_in[2];
    const float* ln_offset = (const float*)d_in[3];
    const float* left_w    = (const float*)d_in[4];
    const float* left_b    = (const float*)d_in[5];
    const float* right_w   = (const float*)d_in[6];
    const float* right_b   = (const float*)d_in[7];
    const float* output_w  = (const float*)d_in[8];
    const float* output_b  = (const float*)d_in[9];
    float* out = (float*)d_out;

    ln_proj_kernel<<<N_SEQ * N_RES, 256>>>(act, mask, ln_scale, ln_offset,
                                           left_w, left_b, right_w, right_b);
    norm_kernel<<<NPAIR / 256, 256>>>(mask);
    gemm1_kernel<<<dim3(BC / 128, BC / 128), 256>>>();
    gemm2_kernel<<<NPAIR / 128, 256>>>(output_w, output_b, out);
}

// round 3
// speedup vs baseline: 1.4163x; 1.4163x over previous
#include <cuda_runtime.h>
#include <cuda_bf16.h>
#include <math.h>
#include <stdint.h>

#define N_SEQ 512
#define N_RES 384
#define C_M   256
#define C_OUT 32
#define C_Z   128
#define BC    (N_RES * C_OUT)     /* 12288  (b,c) flattened */
#define NPAIR (N_RES * N_RES)     /* 147456 (b,d) pairs     */
#define KCE   (C_OUT * C_OUT)     /* 1024   (c,e) flattened */

// ---------------- scratch (device globals; no allocation allowed) ----------
__device__ float g_L[(size_t)N_SEQ * BC];            // fp32 [a, bc]
__device__ float g_R[(size_t)N_SEQ * BC];            // fp32 [a, de]
__device__ float g_interP[(size_t)NPAIR * KCE];      // 604 MB [(b,d), (c,e)]
__device__ float g_ninv[NPAIR];
// split-bf16 K-major operands: [bc|de][a]
__device__ __nv_bfloat16 g_Lhi[(size_t)BC * N_SEQ];
__device__ __nv_bfloat16 g_Llo[(size_t)BC * N_SEQ];
__device__ __nv_bfloat16 g_Rhi[(size_t)BC * N_SEQ];
__device__ __nv_bfloat16 g_Rlo[(size_t)BC * N_SEQ];
// W transposed + split: [f][ce]
__device__ __nv_bfloat16 g_Wt_hi[(size_t)C_Z * KCE];
__device__ __nv_bfloat16 g_Wt_lo[(size_t)C_Z * KCE];

// ======================= PTX helpers (baseline sm_80 features) =============
__device__ __forceinline__ uint32_t smem_u32(const void* p) {
    uint32_t a;
    asm("{ .reg .u64 t; cvta.to.shared.u64 t, %1; cvt.u32.u64 %0, t; }"
        : "=r"(a) : "l"(p));
    return a;
}

#define LDSM_X4(r, addr) \
    asm volatile("ldmatrix.sync.aligned.m8n8.x4.shared.b16 {%0,%1,%2,%3}, [%4];" \
                 : "=r"((r)[0]), "=r"((r)[1]), "=r"((r)[2]), "=r"((r)[3]) \
                 : "r"(addr))

#define MMA_BF16(d, a, b0, b1) \
    asm volatile("mma.sync.aligned.m16n8k16.row.col.f32.bf16.bf16.f32 " \
                 "{%0,%1,%2,%3},{%4,%5,%6,%7},{%8,%9},{%0,%1,%2,%3};" \
                 : "+f"((d)[0]), "+f"((d)[1]), "+f"((d)[2]), "+f"((d)[3]) \
                 : "r"((a)[0]), "r"((a)[1]), "r"((a)[2]), "r"((a)[3]), \
                   "r"(b0), "r"(b1))

__device__ __forceinline__ void split_pack(float x, float y,
                                           uint32_t& hi, uint32_t& lo) {
    __nv_bfloat16 hx = __float2bfloat16(x), hy = __float2bfloat16(y);
    __nv_bfloat16 lx = __float2bfloat16(x - __bfloat162float(hx));
    __nv_bfloat16 ly = __float2bfloat16(y - __bfloat162float(hy));
    hi = (uint32_t)__bfloat16_as_ushort(hx) | ((uint32_t)__bfloat16_as_ushort(hy) << 16);
    lo = (uint32_t)__bfloat16_as_ushort(lx) | ((uint32_t)__bfloat16_as_ushort(ly) << 16);
}

// ---------------- Kernel 1: LayerNorm + left/right projection + mask -------
__global__ __launch_bounds__(256) void ln_proj_kernel(
    const float* __restrict__ act, const float* __restrict__ mask,
    const float* __restrict__ ln_scale, const float* __restrict__ ln_offset,
    const float* __restrict__ left_w, const float* __restrict__ left_b,
    const float* __restrict__ right_w, const float* __restrict__ right_b)
{
    int row = blockIdx.x;              // row = a*N_RES + b
    int t = threadIdx.x;               // 0..255
    __shared__ float ys[C_M];
    __shared__ float red[16];
    __shared__ float ps[16][64];

    float x = act[(size_t)row * C_M + t];
    float s = x, s2 = x * x;
    #pragma unroll
    for (int o = 16; o > 0; o >>= 1) {
        s  += __shfl_down_sync(0xffffffffu, s, o);
        s2 += __shfl_down_sync(0xffffffffu, s2, o);
    }
    int wid = t >> 5, lane = t & 31;
    if (lane == 0) { red[wid] = s; red[wid + 8] = s2; }
    __syncthreads();
    float sum = 0.f, sumsq = 0.f;
    #pragma unroll
    for (int i = 0; i < 8; i++) { sum += red[i]; sumsq += red[i + 8]; }
    float mu  = sum * (1.0f / C_M);
    float var = sumsq * (1.0f / C_M) - mu * mu;
    float y = (x - mu) * rsqrtf(var + 1e-5f) * ln_scale[t] + ln_offset[t];
    ys[t] = y;
    __syncthreads();

    int og = t & 15;
    int ch = t >> 4;
    const float* Wp = (og < 8) ? (left_w + og * 4) : (right_w + (og - 8) * 4);
    float p0 = 0.f, p1 = 0.f, p2 = 0.f, p3 = 0.f;
    #pragma unroll
    for (int i = 0; i < 16; i++) {
        int k = ch * 16 + i;
        float4 w4 = *(const float4*)(Wp + (size_t)k * C_OUT);
        float yv = ys[k];
        p0 += yv * w4.x; p1 += yv * w4.y; p2 += yv * w4.z; p3 += yv * w4.w;
    }
    ps[ch][og * 4 + 0] = p0; ps[ch][og * 4 + 1] = p1;
    ps[ch][og * 4 + 2] = p2; ps[ch][og * 4 + 3] = p3;
    __syncthreads();

    if (t < 64) {
        float v = 0.f;
        #pragma unroll
        for (int c = 0; c < 16; c++) v += ps[c][t];
        float m = mask[row];
        int a = row / N_RES, b = row % N_RES;
        size_t idx = (size_t)a * BC + (size_t)b * C_OUT;
        if (t < 32) g_L[idx + t]        = m * (v + left_b[t]);
        else        g_R[idx + (t - 32)] = m * (v + right_b[t - 32]);
    }
}

// ------------- Kernel 1b: transpose + split into bf16 hi/lo [bc][a] --------
__global__ __launch_bounds__(256) void split_tr_kernel()
{
    __shared__ float t[32][65];
    const float* src = blockIdx.z ? g_R : g_L;
    __nv_bfloat16* dh = blockIdx.z ? g_Rhi : g_Lhi;
    __nv_bfloat16* dl = blockIdx.z ? g_Rlo : g_Llo;
    int c0 = blockIdx.x * 64;       // bc tile
    int a0 = blockIdx.y * 32;       // a tile
    for (int i = threadIdx.x; i < 32 * 64; i += 256) {
        int al = i >> 6, cl = i & 63;
        t[al][cl] = src[(size_t)(a0 + al) * BC + c0 + cl];
    }
    __syncthreads();
    for (int i = threadIdx.x; i < 64 * 32; i += 256) {
        int cl = i >> 5, al = i & 31;
        float x = t[al][cl];
        __nv_bfloat16 hi = __float2bfloat16(x);
        __nv_bfloat16 lo = __float2bfloat16(x - __bfloat162float(hi));
        size_t o = (size_t)(c0 + cl) * N_SEQ + a0 + al;
        dh[o] = hi; dl[o] = lo;
    }
}

// ------------- Kernel 1c: transpose + split output_w -> [f][ce] ------------
__global__ __launch_bounds__(256) void wsplit_kernel(const float* __restrict__ W)
{
    __shared__ float t[32][33];
    int k0 = blockIdx.x * 32;       // ce
    int f0 = blockIdx.y * 32;       // f
    for (int i = threadIdx.x; i < 1024; i += 256) {
        int r = i >> 5, c = i & 31;
        t[r][c] = W[(size_t)(k0 + r) * C_Z + f0 + c];
    }
    __syncthreads();
    for (int i = threadIdx.x; i < 1024; i += 256) {
        int r = i >> 5, c = i & 31;      // r = f local, c = k local
        float x = t[c][r];
        __nv_bfloat16 hi = __float2bfloat16(x);
        __nv_bfloat16 lo = __float2bfloat16(x - __bfloat162float(hi));
        size_t o = (size_t)(f0 + r) * KCE + k0 + c;
        g_Wt_hi[o] = hi; g_Wt_lo[o] = lo;
    }
}

// ---------------- Kernel 2: norm = mask^T mask, stored as reciprocal -------
__global__ __launch_bounds__(256) void norm_kernel(const float* __restrict__ mask)
{
    int m = blockIdx.x * 256 + threadIdx.x;
    int b = m / N_RES, d = m % N_RES;
    float s = 0.f;
    for (int a = 0; a < N_SEQ; a++)
        s += mask[a * N_RES + b] * mask[a * N_RES + d];
    g_ninv[m] = 1.0f / (1e-3f + s);
}

// ============ GEMM common smem geometry: 4 tiles of 128 rows x 80B ==========
#define TILE_B  10240
#define STAGE_B 40960
#define GEMM_SMEM (2 * STAGE_B)

// ---------------- Kernel 3: GEMM1 via mma.sync, split-bf16 -----------------
// inter = L^T R, written PERMUTED: g_interP[(b*384+d)*1024 + c*32 + e]
__global__ __launch_bounds__(256) void gemm1_mma()
{
    extern __shared__ __align__(128) char smem[];
    uint32_t sb = smem_u32(smem);
    int tid = threadIdx.x, lane = tid & 31, wid = tid >> 5;
    int i0 = blockIdx.y * 128;     // bc rows (M)
    int j0 = blockIdx.x * 128;     // de cols (N)
    int m_base = (wid & 1) * 64, n_base = (wid >> 1) * 32;

    const __nv_bfloat16* base[4] = {
        g_Lhi + (size_t)i0 * N_SEQ, g_Llo + (size_t)i0 * N_SEQ,
        g_Rhi + (size_t)j0 * N_SEQ, g_Rlo + (size_t)j0 * N_SEQ };

    int crow[2], ccol[2];
    #pragma unroll
    for (int i = 0; i < 2; i++) {
        int ch = tid + (i << 8);
        crow[i] = ch >> 2; ccol[i] = ch & 3;
    }

    uint32_t arow[4], brow[2];
    #pragma unroll
    for (int mt = 0; mt < 4; mt++)
        arow[mt] = (uint32_t)((m_base + mt * 16 + (lane & 15)) * 80 + (lane >> 4) * 16);
    #pragma unroll
    for (int nt2 = 0; nt2 < 2; nt2++)
        brow[nt2] = (uint32_t)((n_base + nt2 * 16 + (lane & 15)) * 80 + (lane >> 4) * 16);

    float acc[4][4][4];
    #pragma unroll
    for (int a = 0; a < 4; a++)
        #pragma unroll
        for (int b = 0; b < 4; b++)
            #pragma unroll
            for (int c = 0; c < 4; c++) acc[a][b][c] = 0.f;

    uint4 pr[4][2];
    #pragma unroll
    for (int t = 0; t < 4; t++)
        #pragma unroll
        for (int i = 0; i < 2; i++)
            pr[t][i] = *(const uint4*)(base[t] + (size_t)crow[i] * N_SEQ + ccol[i] * 8);

    for (int kt = 0; kt < 16; kt++) {
        char* st = smem + (kt & 1) * STAGE_B;
        #pragma unroll
        for (int t = 0; t < 4; t++)
            #pragma unroll
            for (int i = 0; i < 2; i++)
                *(uint4*)(st + t * TILE_B + crow[i] * 80 + ccol[i] * 16) = pr[t][i];
        if (kt < 15) {
            #pragma unroll
            for (int t = 0; t < 4; t++)
                #pragma unroll
                for (int i = 0; i < 2; i++)
                    pr[t][i] = *(const uint4*)(base[t] + (size_t)crow[i] * N_SEQ
                                               + (kt + 1) * 32 + ccol[i] * 8);
        }
        __syncthreads();
        uint32_t stb = sb + (kt & 1) * STAGE_B;
        #pragma unroll
        for (int ks = 0; ks < 2; ks++) {
            uint32_t ko = ks * 32;
            uint32_t ah[4][4], al[4][4], bh[2][4], bl[2][4];
            #pragma unroll
            for (int mt = 0; mt < 4; mt++) {
                LDSM_X4(ah[mt], stb + arow[mt] + ko);
                LDSM_X4(al[mt], stb + TILE_B + arow[mt] + ko);
            }
            #pragma unroll
            for (int nt2 = 0; nt2 < 2; nt2++) {
                LDSM_X4(bh[nt2], stb + 2 * TILE_B + brow[nt2] + ko);
                LDSM_X4(bl[nt2], stb + 3 * TILE_B + brow[nt2] + ko);
            }
            #pragma unroll
            for (int mt = 0; mt < 4; mt++)
                #pragma unroll
                for (int nt = 0; nt < 4; nt++) {
                    int n2 = nt >> 1, o = nt & 1;
                    MMA_BF16(acc[mt][nt], ah[mt], bh[n2][o], bh[n2][o + 2]);
                    MMA_BF16(acc[mt][nt], ah[mt], bl[n2][o], bl[n2][o + 2]);
                    MMA_BF16(acc[mt][nt], al[mt], bh[n2][o], bh[n2][o + 2]);
                }
        }
        __syncthreads();
    }

    // epilogue: permuted store
    int g = lane >> 2, tg = lane & 3;
    #pragma unroll
    for (int mt = 0; mt < 4; mt++) {
        #pragma unroll
        for (int h = 0; h < 2; h++) {
            int i = i0 + m_base + mt * 16 + g + h * 8;
            int b = i >> 5, c = i & 31;
            #pragma unroll
            for (int nt = 0; nt < 4; nt++) {
                int j = j0 + n_base + nt * 8 + tg * 2;
                int d = j >> 5, e = j & 31;
                float2 v = make_float2(acc[mt][nt][h * 2 + 0], acc[mt][nt][h * 2 + 1]);
                *(float2*)&g_interP[((size_t)(b * N_RES + d) << 10) + c * 32 + e] = v;
            }
        }
    }
}

// ---------------- Kernel 4: GEMM2 via mma.sync, split-bf16 -----------------
// out[m,f] = (sum_k interP[m,k]*Wt[f,k] + ob[f]) * ninv[m];  M=147456,K=1024,N=128
__global__ __launch_bounds__(256) void gemm2_mma(
    const float* __restrict__ ob, float* __restrict__ out)
{
    extern __shared__ __align__(128) char smem[];
    uint32_t sb = smem_u32(smem);
    int tid = threadIdx.x, lane = tid & 31, wid = tid >> 5;
    int m0 = blockIdx.x * 128;
    int m_base = (wid & 1) * 64, n_base = (wid >> 1) * 32;

    const float* Ab = g_interP + (size_t)m0 * KCE;
    const __nv_bfloat16* Wb[2] = { g_Wt_hi, g_Wt_lo };

    int ar[4], ac[4], wr[2], wc[2];
    #pragma unroll
    for (int i = 0; i < 4; i++) {
        int idx = tid + (i << 8);
        ar[i] = idx >> 3; ac[i] = idx & 7;
    }
    #pragma unroll
    for (int i = 0; i < 2; i++) {
        int ch = tid + (i << 8);
        wr[i] = ch >> 2; wc[i] = ch & 3;
    }

    uint32_t arow[4], brow[2];
    #pragma unroll
    for (int mt = 0; mt < 4; mt++)
        arow[mt] = (uint32_t)((m_base + mt * 16 + (lane & 15)) * 80 + (lane >> 4) * 16);
    #pragma unroll
    for (int nt2 = 0; nt2 < 2; nt2++)
        brow[nt2] = (uint32_t)((n_base + nt2 * 16 + (lane & 15)) * 80 + (lane >> 4) * 16);

    float acc[4][4][4];
    #pragma unroll
    for (int a = 0; a < 4; a++)
        #pragma unroll
        for (int b = 0; b < 4; b++)
            #pragma unroll
            for (int c = 0; c < 4; c++) acc[a][b][c] = 0.f;

    float4 pa[4];
    uint4 pw[2][2];
    #pragma unroll
    for (int i = 0; i < 4; i++)
        pa[i] = *(const float4*)(Ab + (size_t)ar[i] * KCE + ac[i] * 4);
    #pragma unroll
    for (int h = 0; h < 2; h++)
        #pragma unroll
        for (int i = 0; i < 2; i++)
            pw[h][i] = *(const uint4*)(Wb[h] + (size_t)wr[i] * KCE + wc[i] * 8);

    for (int kt = 0; kt < 32; kt++) {
        char* st = smem + (kt & 1) * STAGE_B;
        #pragma unroll
        for (int i = 0; i < 4; i++) {
            uint32_t h0, l0, h1, l1;
            split_pack(pa[i].x, pa[i].y, h0, l0);
            split_pack(pa[i].z, pa[i].w, h1, l1);
            *(uint2*)(st + ar[i] * 80 + ac[i] * 8)          = make_uint2(h0, h1);
            *(uint2*)(st + TILE_B + ar[i] * 80 + ac[i] * 8) = make_uint2(l0, l1);
        }
        #pragma unroll
        for (int h = 0; h < 2; h++)
            #pragma unroll
            for (int i = 0; i < 2; i++)
                *(uint4*)(st + (2 + h) * TILE_B + wr[i] * 80 + wc[i] * 16) = pw[h][i];
        if (kt < 31) {
            #pragma unroll
            for (int i = 0; i < 4; i++)
                pa[i] = *(const float4*)(Ab + (size_t)ar[i] * KCE + (kt + 1) * 32 + ac[i] * 4);
            #pragma unroll
            for (int h = 0; h < 2; h++)
                #pragma unroll
                for (int i = 0; i < 2; i++)
                    pw[h][i] = *(const uint4*)(Wb[h] + (size_t)wr[i] * KCE
                                               + (kt + 1) * 32 + wc[i] * 8);
        }
        __syncthreads();
        uint32_t stb = sb + (kt & 1) * STAGE_B;
        #pragma unroll
        for (int ks = 0; ks < 2; ks++) {
            uint32_t ko = ks * 32;
            uint32_t ah[4][4], al[4][4], bh[2][4], bl[2][4];
            #pragma unroll
            for (int mt = 0; mt < 4; mt++) {
                LDSM_X4(ah[mt], stb + arow[mt] + ko);
                LDSM_X4(al[mt], stb + TILE_B + arow[mt] + ko);
            }
            #pragma unroll
            for (int nt2 = 0; nt2 < 2; nt2++) {
                LDSM_X4(bh[nt2], stb + 2 * TILE_B + brow[nt2] + ko);
                LDSM_X4(bl[nt2], stb + 3 * TILE_B + brow[nt2] + ko);
            }
            #pragma unroll
            for (int mt = 0; mt < 4; mt++)
                #pragma unroll
                for (int nt = 0; nt < 4; nt++) {
                    int n2 = nt >> 1, o = nt & 1;
                    MMA_BF16(acc[mt][nt], ah[mt], bh[n2][o], bh[n2][o + 2]);
                    MMA_BF16(acc[mt][nt], ah[mt], bl[n2][o], bl[n2][o + 2]);
                    MMA_BF16(acc[mt][nt], al[mt], bh[n2][o], bh[n2][o + 2]);
                }
        }
        __syncthreads();
    }

    int g = lane >> 2, tg = lane & 3;
    #pragma unroll
    for (int mt = 0; mt < 4; mt++) {
        #pragma unroll
        for (int h = 0; h < 2; h++) {
            int m = m0 + m_base + mt * 16 + g + h * 8;
            float inv = g_ninv[m];
            #pragma unroll
            for (int nt = 0; nt < 4; nt++) {
                int f = n_base + nt * 8 + tg * 2;
                float2 v;
                v.x = (acc[mt][nt][h * 2 + 0] + ob[f + 0]) * inv;
                v.y = (acc[mt][nt][h * 2 + 1] + ob[f + 1]) * inv;
                *(float2*)&out[(size_t)m * C_Z + f] = v;
            }
        }
    }
}

// ---------------------------------------------------------------------------
extern "C" void kernel_launch(void* const* d_in, const int* in_sizes, int n_in,
                              void* d_out, int out_size)
{
    const float* act       = (const float*)d_in[0];
    const float* mask      = (const float*)d_in[1];
    const float* ln_scale  = (const float*)d_in[2];
    const float* ln_offset = (const float*)d_in[3];
    const float* left_w    = (const float*)d_in[4];
    const float* left_b    = (const float*)d_in[5];
    const float* right_w   = (const float*)d_in[6];
    const float* right_b   = (const float*)d_in[7];
    const float* output_w  = (const float*)d_in[8];
    const float* output_b  = (const float*)d_in[9];
    float* out = (float*)d_out;

    cudaFuncSetAttribute(gemm1_mma, cudaFuncAttributeMaxDynamicSharedMemorySize, GEMM_SMEM);
    cudaFuncSetAttribute(gemm2_mma, cudaFuncAttributeMaxDynamicSharedMemorySize, GEMM_SMEM);

    ln_proj_kernel<<<N_SEQ * N_RES, 256>>>(act, mask, ln_scale, ln_offset,
                                           left_w, left_b, right_w, right_b);
    split_tr_kernel<<<dim3(BC / 64, N_SEQ / 32, 2), 256>>>();
    wsplit_kernel<<<dim3(KCE / 32, C_Z / 32), 256>>>(output_w);
    norm_kernel<<<NPAIR / 256, 256>>>(mask);
    gemm1_mma<<<dim3(BC / 128, BC / 128), 256, GEMM_SMEM>>>();
    gemm2_mma<<<NPAIR / 128, 256, GEMM_SMEM>>>(output_b, out);
}

// round 4
// speedup vs baseline: 1.6337x; 1.1535x over previous
#include <cuda_runtime.h>
#include <cuda_bf16.h>
#include <math.h>
#include <stdint.h>

#define N_SEQ 512
#define N_RES 384
#define C_M   256
#define C_OUT 32
#define C_Z   128
#define BC    (N_RES * C_OUT)     /* 12288  (b,c) flattened */
#define NPAIR (N_RES * N_RES)     /* 147456 (b,d) pairs     */
#define KCE   (C_OUT * C_OUT)     /* 1024   (c,e) flattened */

// ---------------- scratch (device globals; no allocation allowed) ----------
__device__ float g_L[(size_t)N_SEQ * BC];            // fp32 [a, bc]
__device__ float g_R[(size_t)N_SEQ * BC];            // fp32 [a, de]
__device__ float g_ninv[NPAIR];
// split-bf16 K-major operands: [bc|de][a]
__device__ __align__(128) __nv_bfloat16 g_Lhi[(size_t)BC * N_SEQ];
__device__ __align__(128) __nv_bfloat16 g_Llo[(size_t)BC * N_SEQ];
__device__ __align__(128) __nv_bfloat16 g_Rhi[(size_t)BC * N_SEQ];
__device__ __align__(128) __nv_bfloat16 g_Rlo[(size_t)BC * N_SEQ];
// inter, PERMUTED [(b,d),(c,e)], pre-split bf16
__device__ __align__(128) __nv_bfloat16 g_iPhi[(size_t)NPAIR * KCE];  // 302 MB
__device__ __align__(128) __nv_bfloat16 g_iPlo[(size_t)NPAIR * KCE];  // 302 MB
// W transposed + split: [f][ce]
__device__ __align__(128) __nv_bfloat16 g_Wt_hi[(size_t)C_Z * KCE];
__device__ __align__(128) __nv_bfloat16 g_Wt_lo[(size_t)C_Z * KCE];

// ======================= PTX helpers (baseline sm_80 features) =============
__device__ __forceinline__ uint32_t smem_u32(const void* p) {
    uint32_t a;
    asm("{ .reg .u64 t; cvta.to.shared.u64 t, %1; cvt.u32.u64 %0, t; }"
        : "=r"(a) : "l"(p));
    return a;
}
#define LDSM_X4(r, addr) \
    asm volatile("ldmatrix.sync.aligned.m8n8.x4.shared.b16 {%0,%1,%2,%3}, [%4];" \
                 : "=r"((r)[0]), "=r"((r)[1]), "=r"((r)[2]), "=r"((r)[3]) \
                 : "r"(addr))
#define MMA_BF16(d, a, b0, b1) \
    asm volatile("mma.sync.aligned.m16n8k16.row.col.f32.bf16.bf16.f32 " \
                 "{%0,%1,%2,%3},{%4,%5,%6,%7},{%8,%9},{%0,%1,%2,%3};" \
                 : "+f"((d)[0]), "+f"((d)[1]), "+f"((d)[2]), "+f"((d)[3]) \
                 : "r"((a)[0]), "r"((a)[1]), "r"((a)[2]), "r"((a)[3]), \
                   "r"(b0), "r"(b1))
#define CP_ASYNC16(dst, src) \
    asm volatile("cp.async.cg.shared.global [%0], [%1], 16;" \
                 :: "r"(dst), "l"(src) : "memory")
#define CP_COMMIT() asm volatile("cp.async.commit_group;" ::: "memory")
#define CP_WAIT(n)  asm volatile("cp.async.wait_group %0;" :: "n"(n) : "memory")

// ---------------- Kernel 1: LayerNorm + left/right projection + mask -------
__global__ __launch_bounds__(256) void ln_proj_kernel(
    const float* __restrict__ act, const float* __restrict__ mask,
    const float* __restrict__ ln_scale, const float* __restrict__ ln_offset,
    const float* __restrict__ left_w, const float* __restrict__ left_b,
    const float* __restrict__ right_w, const float* __restrict__ right_b)
{
    int row = blockIdx.x;              // row = a*N_RES + b
    int t = threadIdx.x;
    __shared__ float ys[C_M];
    __shared__ float red[16];
    __shared__ float ps[16][64];

    float x = act[(size_t)row * C_M + t];
    float s = x, s2 = x * x;
    #pragma unroll
    for (int o = 16; o > 0; o >>= 1) {
        s  += __shfl_down_sync(0xffffffffu, s, o);
        s2 += __shfl_down_sync(0xffffffffu, s2, o);
    }
    int wid = t >> 5, lane = t & 31;
    if (lane == 0) { red[wid] = s; red[wid + 8] = s2; }
    __syncthreads();
    float sum = 0.f, sumsq = 0.f;
    #pragma unroll
    for (int i = 0; i < 8; i++) { sum += red[i]; sumsq += red[i + 8]; }
    float mu  = sum * (1.0f / C_M);
    float var = sumsq * (1.0f / C_M) - mu * mu;
    float y = (x - mu) * rsqrtf(var + 1e-5f) * ln_scale[t] + ln_offset[t];
    ys[t] = y;
    __syncthreads();

    int og = t & 15;
    int ch = t >> 4;
    const float* Wp = (og < 8) ? (left_w + og * 4) : (right_w + (og - 8) * 4);
    float p0 = 0.f, p1 = 0.f, p2 = 0.f, p3 = 0.f;
    #pragma unroll
    for (int i = 0; i < 16; i++) {
        int k = ch * 16 + i;
        float4 w4 = *(const float4*)(Wp + (size_t)k * C_OUT);
        float yv = ys[k];
        p0 += yv * w4.x; p1 += yv * w4.y; p2 += yv * w4.z; p3 += yv * w4.w;
    }
    ps[ch][og * 4 + 0] = p0; ps[ch][og * 4 + 1] = p1;
    ps[ch][og * 4 + 2] = p2; ps[ch][og * 4 + 3] = p3;
    __syncthreads();

    if (t < 64) {
        float v = 0.f;
        #pragma unroll
        for (int c = 0; c < 16; c++) v += ps[c][t];
        float m = mask[row];
        int a = row / N_RES, b = row % N_RES;
        size_t idx = (size_t)a * BC + (size_t)b * C_OUT;
        if (t < 32) g_L[idx + t]        = m * (v + left_b[t]);
        else        g_R[idx + (t - 32)] = m * (v + right_b[t - 32]);
    }
}

// ------------- Kernel 1b: transpose + split into bf16 hi/lo [bc][a] --------
__global__ __launch_bounds__(256) void split_tr_kernel()
{
    __shared__ float t[32][65];
    const float* src = blockIdx.z ? g_R : g_L;
    __nv_bfloat16* dh = blockIdx.z ? g_Rhi : g_Lhi;
    __nv_bfloat16* dl = blockIdx.z ? g_Rlo : g_Llo;
    int c0 = blockIdx.x * 64;
    int a0 = blockIdx.y * 32;
    for (int i = threadIdx.x; i < 32 * 64; i += 256) {
        int al = i >> 6, cl = i & 63;
        t[al][cl] = src[(size_t)(a0 + al) * BC + c0 + cl];
    }
    __syncthreads();
    for (int i = threadIdx.x; i < 64 * 32; i += 256) {
        int cl = i >> 5, al = i & 31;
        float x = t[al][cl];
        __nv_bfloat16 hi = __float2bfloat16(x);
        __nv_bfloat16 lo = __float2bfloat16(x - __bfloat162float(hi));
        size_t o = (size_t)(c0 + cl) * N_SEQ + a0 + al;
        dh[o] = hi; dl[o] = lo;
    }
}

// ------------- Kernel 1c: transpose + split output_w -> [f][ce] ------------
__global__ __launch_bounds__(256) void wsplit_kernel(const float* __restrict__ W)
{
    __shared__ float t[32][33];
    int k0 = blockIdx.x * 32;
    int f0 = blockIdx.y * 32;
    for (int i = threadIdx.x; i < 1024; i += 256) {
        int r = i >> 5, c = i & 31;
        t[r][c] = W[(size_t)(k0 + r) * C_Z + f0 + c];
    }
    __syncthreads();
    for (int i = threadIdx.x; i < 1024; i += 256) {
        int r = i >> 5, c = i & 31;
        float x = t[c][r];
        __nv_bfloat16 hi = __float2bfloat16(x);
        __nv_bfloat16 lo = __float2bfloat16(x - __bfloat162float(hi));
        size_t o = (size_t)(f0 + r) * KCE + k0 + c;
        g_Wt_hi[o] = hi; g_Wt_lo[o] = lo;
    }
}

// ---------------- Kernel 2: norm reciprocal --------------------------------
__global__ __launch_bounds__(256) void norm_kernel(const float* __restrict__ mask)
{
    int m = blockIdx.x * 256 + threadIdx.x;
    int b = m / N_RES, d = m % N_RES;
    float s = 0.f;
    for (int a = 0; a < N_SEQ; a++)
        s += mask[a * N_RES + b] * mask[a * N_RES + d];
    g_ninv[m] = 1.0f / (1e-3f + s);
}

// ============ GEMM smem geometry: 4 tiles of 128 rows x 80B, 2 stages ======
#define TILE_B  10240
#define STAGE_B 40960
#define GEMM_SMEM (2 * STAGE_B)

// inner compute: 128x128 tile step of K=32 (two k=16 halves)
#define GEMM_COMPUTE(stb, arow, brow, acc)                                   \
    _Pragma("unroll")                                                        \
    for (int ks = 0; ks < 2; ks++) {                                         \
        uint32_t ko = ks * 32;                                               \
        uint32_t bh0[4], bh1[4], bl0[4], bl1[4];                             \
        LDSM_X4(bh0, (stb) + 2 * TILE_B + (brow)[0] + ko);                   \
        LDSM_X4(bh1, (stb) + 2 * TILE_B + (brow)[1] + ko);                   \
        LDSM_X4(bl0, (stb) + 3 * TILE_B + (brow)[0] + ko);                   \
        LDSM_X4(bl1, (stb) + 3 * TILE_B + (brow)[1] + ko);                   \
        _Pragma("unroll")                                                    \
        for (int mt = 0; mt < 4; mt++) {                                     \
            uint32_t ah[4], al[4];                                           \
            LDSM_X4(ah, (stb) + (arow)[mt] + ko);                            \
            LDSM_X4(al, (stb) + TILE_B + (arow)[mt] + ko);                   \
            MMA_BF16((acc)[mt][0], ah, bh0[0], bh0[2]);                      \
            MMA_BF16((acc)[mt][0], ah, bl0[0], bl0[2]);                      \
            MMA_BF16((acc)[mt][0], al, bh0[0], bh0[2]);                      \
            MMA_BF16((acc)[mt][1], ah, bh0[1], bh0[3]);                      \
            MMA_BF16((acc)[mt][1], ah, bl0[1], bl0[3]);                      \
            MMA_BF16((acc)[mt][1], al, bh0[1], bh0[3]);                      \
            MMA_BF16((acc)[mt][2], ah, bh1[0], bh1[2]);                      \
            MMA_BF16((acc)[mt][2], ah, bl1[0], bl1[2]);                      \
            MMA_BF16((acc)[mt][2], al, bh1[0], bh1[2]);                      \
            MMA_BF16((acc)[mt][3], ah, bh1[1], bh1[3]);                      \
            MMA_BF16((acc)[mt][3], ah, bl1[1], bl1[3]);                      \
            MMA_BF16((acc)[mt][3], al, bh1[1], bh1[3]);                      \
        }                                                                    \
    }

// ---------------- Kernel 3: GEMM1 = L^T R, epilogue: split-bf16 permuted ---
__global__ __launch_bounds__(256, 2) void gemm1_mma()
{
    extern __shared__ __align__(128) char smem[];
    uint32_t sb = smem_u32(smem);
    int tid = threadIdx.x, lane = tid & 31, wid = tid >> 5;
    int i0 = blockIdx.y * 128;     // bc (M)
    int j0 = blockIdx.x * 128;     // de (N)
    int m_base = (wid & 1) * 64, n_base = (wid >> 1) * 32;

    const __nv_bfloat16* base[4] = {
        g_Lhi + (size_t)i0 * N_SEQ, g_Llo + (size_t)i0 * N_SEQ,
        g_Rhi + (size_t)j0 * N_SEQ, g_Rlo + (size_t)j0 * N_SEQ };

    int crow[2], ccol[2];
    uint32_t soff[2]; int goff[2];
    #pragma unroll
    for (int i = 0; i < 2; i++) {
        int ch = tid + (i << 8);
        crow[i] = ch >> 2; ccol[i] = ch & 3;
        soff[i] = (uint32_t)(crow[i] * 80 + ccol[i] * 16);
        goff[i] = crow[i] * N_SEQ + ccol[i] * 8;
    }

    uint32_t arow[4], brow[2];
    #pragma unroll
    for (int mt = 0; mt < 4; mt++)
        arow[mt] = (uint32_t)((m_base + mt * 16 + (lane & 15)) * 80 + (lane >> 4) * 16);
    #pragma unroll
    for (int n2 = 0; n2 < 2; n2++)
        brow[n2] = (uint32_t)((n_base + n2 * 16 + (lane & 15)) * 80 + (lane >> 4) * 16);

    float acc[4][4][4];
    #pragma unroll
    for (int a = 0; a < 4; a++)
        #pragma unroll
        for (int b = 0; b < 4; b++)
            #pragma unroll
            for (int c = 0; c < 4; c++) acc[a][b][c] = 0.f;

    // prologue: stage 0, kt 0
    #pragma unroll
    for (int t = 0; t < 4; t++)
        #pragma unroll
        for (int i = 0; i < 2; i++)
            CP_ASYNC16(sb + t * TILE_B + soff[i], base[t] + goff[i]);
    CP_COMMIT();

    for (int kt = 0; kt < 16; kt++) {
        if (kt < 15) {
            uint32_t so = (uint32_t)((kt + 1) & 1) * STAGE_B;
            int go = (kt + 1) * 32;
            #pragma unroll
            for (int t = 0; t < 4; t++)
                #pragma unroll
                for (int i = 0; i < 2; i++)
                    CP_ASYNC16(sb + so + t * TILE_B + soff[i], base[t] + goff[i] + go);
            CP_COMMIT();
            CP_WAIT(1);
        } else {
            CP_WAIT(0);
        }
        __syncthreads();
        uint32_t stb = sb + (uint32_t)(kt & 1) * STAGE_B;
        GEMM_COMPUTE(stb, arow, brow, acc);
        __syncthreads();
    }

    // epilogue: permuted split-bf16 store
    int g = lane >> 2, tg = lane & 3;
    #pragma unroll
    for (int mt = 0; mt < 4; mt++) {
        #pragma unroll
        for (int h = 0; h < 2; h++) {
            int i = i0 + m_base + mt * 16 + g + h * 8;
            int b = i >> 5, c = i & 31;
            #pragma unroll
            for (int nt = 0; nt < 4; nt++) {
                int j = j0 + n_base + nt * 8 + tg * 2;
                int d = j >> 5, e = j & 31;
                size_t o = ((size_t)(b * N_RES + d) << 10) + c * 32 + e;
                float x = acc[mt][nt][h * 2 + 0], y = acc[mt][nt][h * 2 + 1];
                __nv_bfloat16 hx = __float2bfloat16(x), hy = __float2bfloat16(y);
                __nv_bfloat16 lx = __float2bfloat16(x - __bfloat162float(hx));
                __nv_bfloat16 ly = __float2bfloat16(y - __bfloat162float(hy));
                *(__nv_bfloat162*)&g_iPhi[o] = __nv_bfloat162(hx, hy);
                *(__nv_bfloat162*)&g_iPlo[o] = __nv_bfloat162(lx, ly);
            }
        }
    }
}

// ---------------- Kernel 4: GEMM2 = interP @ Wt^T + b, / norm --------------
__global__ __launch_bounds__(256, 2) void gemm2_mma(
    const float* __restrict__ ob, float* __restrict__ out)
{
    extern __shared__ __align__(128) char smem[];
    uint32_t sb = smem_u32(smem);
    int tid = threadIdx.x, lane = tid & 31, wid = tid >> 5;
    int m0 = blockIdx.x * 128;
    int m_base = (wid & 1) * 64, n_base = (wid >> 1) * 32;

    const __nv_bfloat16* base[4] = {
        g_iPhi + (size_t)m0 * KCE, g_iPlo + (size_t)m0 * KCE,
        g_Wt_hi, g_Wt_lo };

    int crow[2], ccol[2];
    uint32_t soff[2]; int goff[2];
    #pragma unroll
    for (int i = 0; i < 2; i++) {
        int ch = tid + (i << 8);
        crow[i] = ch >> 2; ccol[i] = ch & 3;
        soff[i] = (uint32_t)(crow[i] * 80 + ccol[i] * 16);
        goff[i] = crow[i] * KCE + ccol[i] * 8;
    }

    uint32_t arow[4], brow[2];
    #pragma unroll
    for (int mt = 0; mt < 4; mt++)
        arow[mt] = (uint32_t)((m_base + mt * 16 + (lane & 15)) * 80 + (lane >> 4) * 16);
    #pragma unroll
    for (int n2 = 0; n2 < 2; n2++)
        brow[n2] = (uint32_t)((n_base + n2 * 16 + (lane & 15)) * 80 + (lane >> 4) * 16);

    float acc[4][4][4];
    #pragma unroll
    for (int a = 0; a < 4; a++)
        #pragma unroll
        for (int b = 0; b < 4; b++)
            #pragma unroll
            for (int c = 0; c < 4; c++) acc[a][b][c] = 0.f;

    #pragma unroll
    for (int t = 0; t < 4; t++)
        #pragma unroll
        for (int i = 0; i < 2; i++)
            CP_ASYNC16(sb + t * TILE_B + soff[i], base[t] + goff[i]);
    CP_COMMIT();

    for (int kt = 0; kt < 32; kt++) {
        if (kt < 31) {
            uint32_t so = (uint32_t)((kt + 1) & 1) * STAGE_B;
            int go = (kt + 1) * 32;
            #pragma unroll
            for (int t = 0; t < 4; t++)
                #pragma unroll
                for (int i = 0; i < 2; i++)
                    CP_ASYNC16(sb + so + t * TILE_B + soff[i], base[t] + goff[i] + go);
            CP_COMMIT();
            CP_WAIT(1);
        } else {
            CP_WAIT(0);
        }
        __syncthreads();
        uint32_t stb = sb + (uint32_t)(kt & 1) * STAGE_B;
        GEMM_COMPUTE(stb, arow, brow, acc);
        __syncthreads();
    }

    int g = lane >> 2, tg = lane & 3;
    #pragma unroll
    for (int mt = 0; mt < 4; mt++) {
        #pragma unroll
        for (int h = 0; h < 2; h++) {
            int m = m0 + m_base + mt * 16 + g + h * 8;
            float inv = g_ninv[m];
            #pragma unroll
            for (int nt = 0; nt < 4; nt++) {
                int f = n_base + nt * 8 + tg * 2;
                float2 v;
                v.x = (acc[mt][nt][h * 2 + 0] + ob[f + 0]) * inv;
                v.y = (acc[mt][nt][h * 2 + 1] + ob[f + 1]) * inv;
                *(float2*)&out[(size_t)m * C_Z + f] = v;
            }
        }
    }
}

// ---------------------------------------------------------------------------
extern "C" void kernel_launch(void* const* d_in, const int* in_sizes, int n_in,
                              void* d_out, int out_size)
{
    const float* act       = (const float*)d_in[0];
    const float* mask      = (const float*)d_in[1];
    const float* ln_scale  = (const float*)d_in[2];
    const float* ln_offset = (const float*)d_in[3];
    const float* left_w    = (const float*)d_in[4];
    const float* left_b    = (const float*)d_in[5];
    const float* right_w   = (const float*)d_in[6];
    const float* right_b   = (const float*)d_in[7];
    const float* output_w  = (const float*)d_in[8];
    const float* output_b  = (const float*)d_in[9];
    float* out = (float*)d_out;

    cudaFuncSetAttribute(gemm1_mma, cudaFuncAttributeMaxDynamicSharedMemorySize, GEMM_SMEM);
    cudaFuncSetAttribute(gemm2_mma, cudaFuncAttributeMaxDynamicSharedMemorySize, GEMM_SMEM);

    // order chosen so the profiler's captured launch (4th) is gemm1
    ln_proj_kernel<<<N_SEQ * N_RES, 256>>>(act, mask, ln_scale, ln_offset,
                                           left_w, left_b, right_w, right_b);
    split_tr_kernel<<<dim3(BC / 64, N_SEQ / 32, 2), 256>>>();
    norm_kernel<<<NPAIR / 256, 256>>>(mask);
    gemm1_mma<<<dim3(BC / 128, BC / 128), 256, GEMM_SMEM>>>();
    wsplit_kernel<<<dim3(KCE / 32, C_Z / 32), 256>>>(output_w);
    gemm2_mma<<<NPAIR / 128, 256, GEMM_SMEM>>>(output_b, out);
}